// round 14
// baseline (speedup 1.0000x reference)
#include <cuda_runtime.h>
#include <cuda_fp16.h>
#include <cstdint>

// Problem constants
#define BATCH   32
#define CIN     256
#define NPIX    4096          // 64*64
#define HEADS   4
#define DH      32
#define HID     128           // HEADS*DH
#define O3      384           // 3*HID
#define EPS     1e-5f
#define PW      (NPIX / 2)    // fp16-pair words per row (2048)

// ---------------------------------------------------------------------------
// Scratch (device globals: allocation-free)
// ---------------------------------------------------------------------------
__device__ uint32_t g_qkvh[(size_t)BATCH * O3 * PW];          // 100 MB exp(q),exp(k),v
__device__ uint32_t g_attn[(size_t)BATCH * (HID/2) * NPIX];   //  34 MB packed along hid
__device__ uint32_t g_outh[(size_t)BATCH * CIN * PW];         //  67 MB out-proj fp16
__device__ float    g_stats[BATCH * 2];
__device__ float    g_ksum [BATCH * HEADS * 32];
__device__ float    g_ctx  [BATCH * HEADS * 32 * 32];

#define N_CTX  (BATCH * HEADS * 32 * 32)
#define N_KSUM (BATCH * HEADS * 32)
#define ZERO_N (N_CTX + N_KSUM + BATCH * 2)
__global__ void k_zero() {
    const int i = blockIdx.x * blockDim.x + threadIdx.x;
    if (i < N_CTX) g_ctx[i] = 0.f;
    else if (i < N_CTX + N_KSUM) g_ksum[i - N_CTX] = 0.f;
    else if (i < ZERO_N) g_stats[i - N_CTX - N_KSUM] = 0.f;
}

// no-op pad: shifts the profiled launch slot (index 3) onto the QKV GEMM
__global__ void k_noop() {}

// ---------------------------------------------------------------------------
// helpers (sm_75/80-baseline PTX)
// ---------------------------------------------------------------------------
__device__ __forceinline__ uint32_t pack2(float lo, float hi) {
    __half2 h = __floats2half2_rn(lo, hi);
    return *reinterpret_cast<uint32_t*>(&h);
}
__device__ __forceinline__ void mma_f16(float c[4],
                                        const uint32_t a[4],
                                        const uint32_t b[2]) {
    asm volatile(
        "mma.sync.aligned.m16n8k16.row.col.f32.f16.f16.f32 "
        "{%0,%1,%2,%3}, {%4,%5,%6,%7}, {%8,%9}, {%0,%1,%2,%3};"
        : "+f"(c[0]), "+f"(c[1]), "+f"(c[2]), "+f"(c[3])
        : "r"(a[0]), "r"(a[1]), "r"(a[2]), "r"(a[3]),
          "r"(b[0]), "r"(b[1]));
}
__device__ __forceinline__ void ldmx4(uint32_t a[4], uint32_t addr) {
    asm volatile(
        "ldmatrix.sync.aligned.m8n8.x4.shared.b16 {%0,%1,%2,%3}, [%4];"
        : "=r"(a[0]), "=r"(a[1]), "=r"(a[2]), "=r"(a[3]) : "r"(addr));
}

// ---------------------------------------------------------------------------
// fp16 tensor-core GEMM:  C[z][M][4096] = A[M,K] * B[z][K,4096]
// CTA tile 128x128, BK=16, 8 warps (2m x 4n), warp tile 64x32.
// 4-stage smem ring, STS->compute distance 2 (one barrier per iter).
// A fragments via ldmatrix.x4. MODE 0: QKV epilogue. MODE 1: out-proj.
// ---------------------------------------------------------------------------
template<int K, int M, int MODE, bool BPK>
__global__ __launch_bounds__(256)
void k_mma(const float* __restrict__ A, const void* __restrict__ Bg_,
           void* __restrict__ Cg, const float* __restrict__ bias)
{
    __shared__ uint32_t As[4][128][8];
    __shared__ uint32_t Bs[4][8][128];

    const int tid  = threadIdx.x, lane = tid & 31, wid = tid >> 5;
    const int wm   = wid >> 2, wn = wid & 3;
    const int tq   = lane & 3, gp = lane >> 2;
    const int mt   = blockIdx.x, nt = blockIdx.y, z = blockIdx.z;

    const float* Ap = A + (size_t)mt * 128 * K;
    const float*    Bpf = BPK ? nullptr
                     : (const float*)Bg_ + (size_t)z * K * NPIX + nt * 128;
    const uint32_t* Bpp = BPK
                     ? (const uint32_t*)Bg_ + (size_t)z * (K/2) * NPIX + nt * 128
                     : nullptr;

    const int am  = tid & 127, akw = (tid >> 7) * 4;
    const int bkw = tid >> 5;
    const int bn0 = lane * 4;

    // ldmatrix lane addressing (within one As stage)
    const int lr = lane & 7;
    const int row_in = ((lane & 8) ? 8 : 0) + lr;
    const int wb = (((lane & 16) ? 4 : 0)) ^ (lr & 4);
    const uint32_t asA =
        (uint32_t)__cvta_generic_to_shared(&As[0][0][0]);
    const uint32_t a_lane_off =
        (uint32_t)(((wm * 64 + row_in) * 8 + wb) * 4);

    float acc[4][4][4];
    #pragma unroll
    for (int i = 0; i < 4; i++)
        #pragma unroll
        for (int j = 0; j < 4; j++)
            #pragma unroll
            for (int r = 0; r < 4; r++) acc[i][j][r] = 0.f;

    float4 ra[2];
    float4 rbf[2];
    uint4  rbp;

    auto ldgA = [&](int t) {
        #pragma unroll
        for (int j = 0; j < 2; j++)
            ra[j] = *(const float4*)(Ap + (size_t)am * K + t * 16 + akw * 2 + j * 4);
    };
    auto stsA = [&](int t) {
        const int buf = t & 3;
        uint32_t w0 = pack2(ra[0].x, ra[0].y);
        uint32_t w1 = pack2(ra[0].z, ra[0].w);
        uint32_t w2 = pack2(ra[1].x, ra[1].y);
        uint32_t w3 = pack2(ra[1].z, ra[1].w);
        *(uint4*)&As[buf][am][akw ^ (am & 4)] = make_uint4(w0, w1, w2, w3);
    };
    auto ldgB = [&](int t) {
        if (BPK) {
            rbp = *(const uint4*)(Bpp + (size_t)(t * 8 + bkw) * NPIX + bn0);
        } else {
            rbf[0] = *(const float4*)(Bpf + (size_t)(t * 16 + 2 * bkw    ) * NPIX + bn0);
            rbf[1] = *(const float4*)(Bpf + (size_t)(t * 16 + 2 * bkw + 1) * NPIX + bn0);
        }
    };
    auto stsB = [&](int t) {
        const int buf = t & 3;
        const int col = bn0 ^ ((bkw & 3) * 8);
        if (BPK) {
            *(uint4*)&Bs[buf][bkw][col] = rbp;
        } else {
            *(uint4*)&Bs[buf][bkw][col] = make_uint4(
                pack2(rbf[0].x, rbf[1].x), pack2(rbf[0].y, rbf[1].y),
                pack2(rbf[0].z, rbf[1].z), pack2(rbf[0].w, rbf[1].w));
        }
    };
    auto compute = [&](int t) {
        const int buf = t & 3;
        const uint32_t abase = asA + (uint32_t)(buf * 128 * 8 * 4) + a_lane_off;
        uint32_t bf[4][2];
        #pragma unroll
        for (int nf = 0; nf < 4; nf++) {
            const int col = (wn * 32 + nf * 8 + gp) ^ (tq * 8);
            bf[nf][0] = Bs[buf][tq    ][col];
            bf[nf][1] = Bs[buf][tq + 4][col];
        }
        #pragma unroll
        for (int mf = 0; mf < 4; mf++) {
            uint32_t af[4];
            ldmx4(af, abase + (uint32_t)(mf * 16 * 8 * 4));
            #pragma unroll
            for (int nf = 0; nf < 4; nf++)
                mma_f16(acc[mf][nf], af, bf[nf]);
        }
    };

    constexpr int T = K / 16;   // 16 (QKV) or 8 (out-proj)

    // prologue: stages 0,1 stored; ldg(2) in regs
    ldgA(0); ldgB(0);
    stsA(0); stsB(0);
    ldgA(1); ldgB(1);
    stsA(1); stsB(1);
    ldgA(2); ldgB(2);
    __syncthreads();

    #pragma unroll 1
    for (int t = 0; t < T; t++) {
        compute(t);
        if (t + 2 < T) { stsA(t + 2); stsB(t + 2); }   // stage (t+2)&3: last read compute(t-2)
        if (t + 3 < T) { ldgA(t + 3); ldgB(t + 3); }
        __syncthreads();
    }

    const int mg0 = mt * 128 + wm * 64;
    const int ng0 = nt * 128 + wn * 32;
    uint32_t* Cw = (uint32_t*)Cg + (size_t)z * M * PW;

    if (MODE == 0) {
        // --- QKV epilogue: exp on q,k + pack fp16 + ksum ---
        #pragma unroll
        for (int mf = 0; mf < 4; mf++) {
            const int r0 = mg0 + mf * 16 + gp;
            float s0 = 0.f, s1 = 0.f;
            #pragma unroll
            for (int nf = 0; nf < 4; nf++) {
                const int wc = (ng0 >> 1) + nf * 4 + tq;
                float a0 = acc[mf][nf][0], a1 = acc[mf][nf][1];
                float a2 = acc[mf][nf][2], a3 = acc[mf][nf][3];
                if (mt < 2) {
                    a0 = __expf(a0); a1 = __expf(a1);
                    a2 = __expf(a2); a3 = __expf(a3);
                }
                s0 += a0 + a1; s1 += a2 + a3;
                Cw[(size_t)r0      * PW + wc] = pack2(a0, a1);
                Cw[(size_t)(r0+8)  * PW + wc] = pack2(a2, a3);
            }
            if (mt == 1) {
                s0 += __shfl_xor_sync(0xffffffffu, s0, 1);
                s0 += __shfl_xor_sync(0xffffffffu, s0, 2);
                s1 += __shfl_xor_sync(0xffffffffu, s1, 1);
                s1 += __shfl_xor_sync(0xffffffffu, s1, 2);
                if (tq == 0) {
                    const int rk  = wm * 64 + mf * 16 + gp;
                    const int rk8 = rk + 8;
                    atomicAdd(&g_ksum[(z * HEADS + (rk  >> 5)) * 32 + (rk  & 31)], s0);
                    atomicAdd(&g_ksum[(z * HEADS + (rk8 >> 5)) * 32 + (rk8 & 31)], s1);
                }
            }
        }
    } else {
        // --- OUT epilogue: bias + stats (fp32 accs), packed fp16 store ---
        float lsum = 0.f, lsq = 0.f;
        #pragma unroll
        for (int mf = 0; mf < 4; mf++) {
            const int r0 = mg0 + mf * 16 + gp;
            const float bv0 = bias[r0];
            const float bv1 = bias[r0 + 8];
            #pragma unroll
            for (int nf = 0; nf < 4; nf++) {
                const int wc = (ng0 >> 1) + nf * 4 + tq;
                float a0 = acc[mf][nf][0] + bv0, a1 = acc[mf][nf][1] + bv0;
                float a2 = acc[mf][nf][2] + bv1, a3 = acc[mf][nf][3] + bv1;
                lsum += a0 + a1 + a2 + a3;
                lsq  += a0 * a0 + a1 * a1 + a2 * a2 + a3 * a3;
                Cw[(size_t)r0      * PW + wc] = pack2(a0, a1);
                Cw[(size_t)(r0+8)  * PW + wc] = pack2(a2, a3);
            }
        }
        __shared__ float rs[8], rq[8];
        #pragma unroll
        for (int o = 16; o; o >>= 1) {
            lsum += __shfl_xor_sync(0xffffffffu, lsum, o);
            lsq  += __shfl_xor_sync(0xffffffffu, lsq,  o);
        }
        if (lane == 0) { rs[wid] = lsum; rq[wid] = lsq; }
        __syncthreads();
        if (tid == 0) {
            float s = 0.f, q = 0.f;
            #pragma unroll
            for (int w = 0; w < 8; w++) { s += rs[w]; q += rq[w]; }
            atomicAdd(&g_stats[2 * z + 0], s);
            atomicAdd(&g_stats[2 * z + 1], q);
        }
    }
}

// ---------------------------------------------------------------------------
// K2b: ctx = expk @ v^T, pure fp16 MMA, gmem-direct fragments (unchanged)
// ---------------------------------------------------------------------------
__global__ __launch_bounds__(256)
void k_ctx()
{
    __shared__ float red[8][32][33];

    const int nt = blockIdx.x, h = blockIdx.y, b = blockIdx.z;
    const int tid = threadIdx.x, lane = tid & 31, w = tid >> 5;
    const int gp = lane >> 2, tq = lane & 3;
    const int bh = b * HEADS + h;

    const uint32_t* kw = g_qkvh + ((size_t)b * O3 + HID     + h * DH) * PW;
    const uint32_t* vw = g_qkvh + ((size_t)b * O3 + 2 * HID + h * DH) * PW;
    const int wb0 = nt * 512 + w * 64;

    float acc[2][4][4];
    #pragma unroll
    for (int i = 0; i < 2; i++)
        #pragma unroll
        for (int j = 0; j < 4; j++)
            #pragma unroll
            for (int r = 0; r < 4; r++) acc[i][j][r] = 0.f;

    #pragma unroll
    for (int kk = 0; kk < 8; kk++) {
        const int w0 = wb0 + kk * 8 + tq, w1 = w0 + 4;
        uint32_t af[2][4], bf[4][2];
        #pragma unroll
        for (int m2 = 0; m2 < 2; m2++) {
            const int dm = m2 * 16;
            af[m2][0] = kw[(size_t)(dm + gp    ) * PW + w0];
            af[m2][1] = kw[(size_t)(dm + gp + 8) * PW + w0];
            af[m2][2] = kw[(size_t)(dm + gp    ) * PW + w1];
            af[m2][3] = kw[(size_t)(dm + gp + 8) * PW + w1];
        }
        #pragma unroll
        for (int n2 = 0; n2 < 4; n2++) {
            const int en = n2 * 8;
            bf[n2][0] = vw[(size_t)(en + gp) * PW + w0];
            bf[n2][1] = vw[(size_t)(en + gp) * PW + w1];
        }
        #pragma unroll
        for (int m2 = 0; m2 < 2; m2++)
            #pragma unroll
            for (int n2 = 0; n2 < 4; n2++)
                mma_f16(acc[m2][n2], af[m2], bf[n2]);
    }

    #pragma unroll
    for (int m2 = 0; m2 < 2; m2++) {
        const int d = m2 * 16 + gp;
        #pragma unroll
        for (int n2 = 0; n2 < 4; n2++) {
            const int e = n2 * 8 + tq * 2;
            red[w][d    ][e    ] = acc[m2][n2][0];
            red[w][d    ][e + 1] = acc[m2][n2][1];
            red[w][d + 8][e    ] = acc[m2][n2][2];
            red[w][d + 8][e + 1] = acc[m2][n2][3];
        }
    }
    __syncthreads();

    #pragma unroll
    for (int c = tid * 4; c < tid * 4 + 4; c++) {
        float s = 0.f;
        #pragma unroll
        for (int ww = 0; ww < 8; ww++) s += red[ww][c >> 5][c & 31];
        atomicAdd(&g_ctx[bh * 1024 + c], s);
    }
}

// ---------------------------------------------------------------------------
// K2c: out = (ctx/ksum)^T * expq * scale/colsum; fp16-packed output (unchanged)
// ---------------------------------------------------------------------------
__global__ __launch_bounds__(256)
void k_qout()
{
    __shared__ float qs[32][257];
    __shared__ float ctx[32][33];
    __shared__ float inv[32];
    __shared__ float cs[2][256];
    __shared__ float cinv[256];

    const int nt = blockIdx.x, h = blockIdx.y, b = blockIdx.z;
    const int tid = threadIdx.x;
    const int bh = b * HEADS + h;

    if (tid < 32) inv[tid] = 1.f / g_ksum[bh * 32 + tid];
    __syncthreads();
    #pragma unroll
    for (int i = tid; i < 1024; i += 256)
        ctx[i >> 5][i & 31] = g_ctx[bh * 1024 + i] * inv[i >> 5];

    const uint32_t* qw = g_qkvh + ((size_t)b * O3 + h * DH) * PW + nt * 128;
    const int wd = tid & 127, g2 = tid >> 7;
    float s0 = 0.f, s1 = 0.f;
    #pragma unroll
    for (int i = 0; i < 16; i++) {
        const int d = g2 + i * 2;
        float2 f = __half22float2(*(const __half2*)&qw[(size_t)d * PW + wd]);
        qs[d][2 * wd    ] = f.x;
        qs[d][2 * wd + 1] = f.y;
        s0 += f.x; s1 += f.y;
    }
    cs[g2][2 * wd    ] = s0;
    cs[g2][2 * wd + 1] = s1;
    __syncthreads();
    cinv[tid] = 0.17677669529663687f / (cs[0][tid] + cs[1][tid]);
    __syncthreads();

    const int w = tid >> 5, lane = tid & 31;
    float acc[4][8];
    #pragma unroll
    for (int i = 0; i < 4; i++)
        #pragma unroll
        for (int j = 0; j < 8; j++) acc[i][j] = 0.f;

    #pragma unroll
    for (int d = 0; d < 32; d++) {
        float ca[4], qa[8];
        #pragma unroll
        for (int i = 0; i < 4; i++) ca[i] = ctx[d][w * 4 + i];
        #pragma unroll
        for (int j = 0; j < 8; j++) qa[j] = qs[d][lane + 32 * j];
        #pragma unroll
        for (int i = 0; i < 4; i++)
            #pragma unroll
            for (int j = 0; j < 8; j++)
                acc[i][j] += ca[i] * qa[j];
    }

    uint32_t* obase = g_attn + ((size_t)b * (HID/2)) * NPIX + nt * 256;
    const int kw0 = h * 16 + w * 2;
    #pragma unroll
    for (int j = 0; j < 8; j++) {
        const int n = lane + 32 * j;
        const float civ = cinv[n];
        obase[(size_t)kw0       * NPIX + n] = pack2(acc[0][j] * civ, acc[1][j] * civ);
        obase[(size_t)(kw0 + 1) * NPIX + n] = pack2(acc[2][j] * civ, acc[3][j] * civ);
    }
}

// ---------------------------------------------------------------------------
// K4: GroupNorm from packed fp16 out-proj result -> fp32 d_out
// ---------------------------------------------------------------------------
__global__ __launch_bounds__(256)
void k_gn(float* __restrict__ out,
          const float* __restrict__ gn_w,
          const float* __restrict__ gn_b)
{
    const size_t widx = ((size_t)blockIdx.x * blockDim.x + threadIdx.x) * 2;
    const int b = (int)(widx >> 19);
    const int c = (int)((widx >> 11) & 255);

    const float invN = 1.f / (256.f * 4096.f);
    const float mean = g_stats[2 * b + 0] * invN;
    const float var  = g_stats[2 * b + 1] * invN - mean * mean;
    const float r    = rsqrtf(var + EPS);
    const float w    = gn_w[c] * r;
    const float bb   = gn_b[c] - mean * w;

    const uint2 pw = *(const uint2*)&g_outh[widx];
    const float2 f0 = __half22float2(*(const __half2*)&pw.x);
    const float2 f1 = __half22float2(*(const __half2*)&pw.y);
    float4 v;
    v.x = f0.x * w + bb;
    v.y = f0.y * w + bb;
    v.z = f1.x * w + bb;
    v.w = f1.y * w + bb;
    *(float4*)&out[widx * 2] = v;
}

// ---------------------------------------------------------------------------
// Launch
// ---------------------------------------------------------------------------
extern "C" void kernel_launch(void* const* d_in, const int* in_sizes, int n_in,
                              void* d_out, int out_size)
{
    const float* x     = (const float*)d_in[0];
    const float* w_qkv = (const float*)d_in[1];
    const float* w_out = (const float*)d_in[2];
    const float* b_out = (const float*)d_in[3];
    const float* gn_w  = (const float*)d_in[4];
    const float* gn_b  = (const float*)d_in[5];
    float* out = (float*)d_out;

    uint32_t *p_qkvh, *p_attn, *p_outh;
    cudaGetSymbolAddress((void**)&p_qkvh, g_qkvh);
    cudaGetSymbolAddress((void**)&p_attn, g_attn);
    cudaGetSymbolAddress((void**)&p_outh, g_outh);

    // launches 0-2: zero + pads (puts the QKV GEMM at profiled slot 3)
    k_zero<<<(ZERO_N + 255) / 256, 256>>>();
    k_noop<<<1, 32>>>();
    k_noop<<<1, 32>>>();

    // launch 3: QKV projection (fp16 HMMA + ldmatrix, 4-stage pipeline)
    k_mma<CIN, O3, 0, false>
        <<<dim3(O3 / 128, NPIX / 128, BATCH), 256>>>(w_qkv, x, p_qkvh, nullptr);

    // attention core
    k_ctx <<<dim3(NPIX / 1024, HEADS, BATCH), 256>>>();
    k_qout<<<dim3(NPIX / 256,  HEADS, BATCH), 256>>>();

    // output projection + bias + stats -> packed fp16
    k_mma<HID, CIN, 1, true>
        <<<dim3(CIN / 128, NPIX / 128, BATCH), 256>>>(w_out, p_attn, p_outh, b_out);

    // GroupNorm fp16 -> fp32 d_out
    k_gn<<<(BATCH * CIN * PW / 2) / 256, 256>>>(out, gn_w, gn_b);
}

// round 16
// speedup vs baseline: 1.1291x; 1.1291x over previous
#include <cuda_runtime.h>
#include <cuda_fp16.h>
#include <cstdint>

// Problem constants
#define BATCH   32
#define CIN     256
#define NPIX    4096          // 64*64
#define HEADS   4
#define DH      32
#define HID     128           // HEADS*DH
#define O3      384           // 3*HID
#define EPS     1e-5f
#define PW      (NPIX / 2)    // fp16-pair words per row (2048)

// ---------------------------------------------------------------------------
// Scratch (device globals: allocation-free)
// ---------------------------------------------------------------------------
__device__ uint32_t g_qkvh[(size_t)BATCH * O3 * PW];          // 100 MB exp(q),exp(k),v
__device__ uint32_t g_attn[(size_t)BATCH * (HID/2) * NPIX];   //  34 MB packed along hid
__device__ uint32_t g_outh[(size_t)BATCH * CIN * PW];         //  67 MB out-proj fp16
__device__ float    g_stats[BATCH * 2];
__device__ float    g_ksum [BATCH * HEADS * 32];
__device__ float    g_ctx  [BATCH * HEADS * 32 * 32];

#define N_CTX  (BATCH * HEADS * 32 * 32)
#define N_KSUM (BATCH * HEADS * 32)
#define ZERO_N (N_CTX + N_KSUM + BATCH * 2)
__global__ void k_zero() {
    const int i = blockIdx.x * blockDim.x + threadIdx.x;
    if (i < N_CTX) g_ctx[i] = 0.f;
    else if (i < N_CTX + N_KSUM) g_ksum[i - N_CTX] = 0.f;
    else if (i < ZERO_N) g_stats[i - N_CTX - N_KSUM] = 0.f;
}

// no-op pads: keep the QKV GEMM at profiled launch slot 3
__global__ void k_noop() {}

// ---------------------------------------------------------------------------
// helpers (sm_75/80-baseline PTX)
// ---------------------------------------------------------------------------
__device__ __forceinline__ uint32_t pack2(float lo, float hi) {
    __half2 h = __floats2half2_rn(lo, hi);
    return *reinterpret_cast<uint32_t*>(&h);
}
__device__ __forceinline__ void mma_f16(float c[4],
                                        const uint32_t a[4],
                                        const uint32_t b[2]) {
    asm volatile(
        "mma.sync.aligned.m16n8k16.row.col.f32.f16.f16.f32 "
        "{%0,%1,%2,%3}, {%4,%5,%6,%7}, {%8,%9}, {%0,%1,%2,%3};"
        : "+f"(c[0]), "+f"(c[1]), "+f"(c[2]), "+f"(c[3])
        : "r"(a[0]), "r"(a[1]), "r"(a[2]), "r"(a[3]),
          "r"(b[0]), "r"(b[1]));
}
__device__ __forceinline__ void ldmx4(uint32_t a[4], uint32_t addr) {
    asm volatile(
        "ldmatrix.sync.aligned.m8n8.x4.shared.b16 {%0,%1,%2,%3}, [%4];"
        : "=r"(a[0]), "=r"(a[1]), "=r"(a[2]), "=r"(a[3]) : "r"(addr));
}

// ---------------------------------------------------------------------------
// fp16 tensor-core GEMM:  C[z][M][4096] = A[M,K] * B[z][K,4096]
// CTA tile 128m x 256n, BK=16, 8 warps (2m x 4n), warp tile 64x64.
// 2.1 L1-wavefronts/MMA (vs 3.0 at 128x128) -- targets the measured L1=87%.
// 4-stage smem ring. A frags via ldmatrix.x4.
// B swizzle is (bkw&3)<<3: the fragment loader reads rows tq and tq+4 at the
// SAME column, so swizzle(tq) must equal swizzle(tq+4). (R15 bug: xor term.)
// MODE 0: QKV epilogue (exp q,k + pack + ksum). MODE 1: out-proj epilogue.
// ---------------------------------------------------------------------------
#define NT 256
#define MMA_SMEM ((4 * 128 * 8 + 4 * 8 * NT) * 4)   // 48 KB dynamic

template<int K, int M, int MODE, bool BPK>
__global__ __launch_bounds__(256)
void k_mma(const float* __restrict__ A, const void* __restrict__ Bg_,
           void* __restrict__ Cg, const float* __restrict__ bias)
{
    extern __shared__ uint32_t dsm[];
    uint32_t (*As)[128][8]  = (uint32_t (*)[128][8])dsm;            // 4 stages
    uint32_t (*Bs)[8][NT]   = (uint32_t (*)[8][NT])(dsm + 4*128*8); // 4 stages

    const int tid  = threadIdx.x, lane = tid & 31, wid = tid >> 5;
    const int wm   = wid >> 2, wn = wid & 3;          // 2m x 4n, warp 64x64
    const int tq   = lane & 3, gp = lane >> 2;
    const int mt   = blockIdx.x, nt = blockIdx.y, z = blockIdx.z;

    const float* Ap = A + (size_t)mt * 128 * K;
    const float*    Bpf = BPK ? nullptr
                     : (const float*)Bg_ + (size_t)z * K * NPIX + nt * NT;
    const uint32_t* Bpp = BPK
                     ? (const uint32_t*)Bg_ + (size_t)z * (K/2) * NPIX + nt * NT
                     : nullptr;

    // A loader: row am, word base akw (2 float4 = 8 k)
    const int am  = tid & 127, akw = (tid >> 7) * 4;
    // B loader: k-pair row bkw (0..7); lane covers word cols 4*lane, 128+4*lane
    const int bkw = tid >> 5;
    const int bswz = (bkw & 3) << 3;          // FIXED: swz(tq) == swz(tq+4)
    const int bc0 = (4 * lane) ^ bswz;
    const int bc1 = (128 + 4 * lane) ^ bswz;

    // ldmatrix lane addressing (within one As stage)
    const int lr = lane & 7;
    const int row_in = ((lane & 8) ? 8 : 0) + lr;
    const int wb = (((lane & 16) ? 4 : 0)) ^ (lr & 4);
    const uint32_t asA = (uint32_t)__cvta_generic_to_shared(&As[0][0][0]);
    const uint32_t a_lane_off = (uint32_t)(((wm * 64 + row_in) * 8 + wb) * 4);

    float acc[4][8][4];
    #pragma unroll
    for (int i = 0; i < 4; i++)
        #pragma unroll
        for (int j = 0; j < 8; j++)
            #pragma unroll
            for (int r = 0; r < 4; r++) acc[i][j][r] = 0.f;

    float4 ra[2];
    float4 rbf[4];
    uint4  rbp[2];

    auto ldgA = [&](int t) {
        #pragma unroll
        for (int j = 0; j < 2; j++)
            ra[j] = *(const float4*)(Ap + (size_t)am * K + t * 16 + akw * 2 + j * 4);
    };
    auto stsA = [&](int t) {
        const int buf = t & 3;
        uint32_t w0 = pack2(ra[0].x, ra[0].y);
        uint32_t w1 = pack2(ra[0].z, ra[0].w);
        uint32_t w2 = pack2(ra[1].x, ra[1].y);
        uint32_t w3 = pack2(ra[1].z, ra[1].w);
        *(uint4*)&As[buf][am][akw ^ (am & 4)] = make_uint4(w0, w1, w2, w3);
    };
    auto ldgB = [&](int t) {
        if (BPK) {
            const uint32_t* r = Bpp + (size_t)(t * 8 + bkw) * NPIX;
            rbp[0] = *(const uint4*)(r + 4 * lane);
            rbp[1] = *(const uint4*)(r + 128 + 4 * lane);
        } else {
            const float* r0 = Bpf + (size_t)(t * 16 + 2 * bkw    ) * NPIX;
            const float* r1 = Bpf + (size_t)(t * 16 + 2 * bkw + 1) * NPIX;
            rbf[0] = *(const float4*)(r0 + 4 * lane);
            rbf[1] = *(const float4*)(r1 + 4 * lane);
            rbf[2] = *(const float4*)(r0 + 128 + 4 * lane);
            rbf[3] = *(const float4*)(r1 + 128 + 4 * lane);
        }
    };
    auto stsB = [&](int t) {
        const int buf = t & 3;
        if (BPK) {
            *(uint4*)&Bs[buf][bkw][bc0] = rbp[0];
            *(uint4*)&Bs[buf][bkw][bc1] = rbp[1];
        } else {
            *(uint4*)&Bs[buf][bkw][bc0] = make_uint4(
                pack2(rbf[0].x, rbf[1].x), pack2(rbf[0].y, rbf[1].y),
                pack2(rbf[0].z, rbf[1].z), pack2(rbf[0].w, rbf[1].w));
            *(uint4*)&Bs[buf][bkw][bc1] = make_uint4(
                pack2(rbf[2].x, rbf[3].x), pack2(rbf[2].y, rbf[3].y),
                pack2(rbf[2].z, rbf[3].z), pack2(rbf[2].w, rbf[3].w));
        }
    };
    auto compute = [&](int t) {
        const int buf = t & 3;
        const uint32_t abase = asA + (uint32_t)(buf * 128 * 8 * 4) + a_lane_off;
        uint32_t bf[8][2];
        #pragma unroll
        for (int nf = 0; nf < 8; nf++) {
            const int col = (wn * 64 + nf * 8 + gp) ^ (tq * 8);
            bf[nf][0] = Bs[buf][tq    ][col];
            bf[nf][1] = Bs[buf][tq + 4][col];
        }
        #pragma unroll
        for (int mf = 0; mf < 4; mf++) {
            uint32_t af[4];
            ldmx4(af, abase + (uint32_t)(mf * 16 * 8 * 4));
            #pragma unroll
            for (int nf = 0; nf < 8; nf++)
                mma_f16(acc[mf][nf], af, bf[nf]);
        }
    };

    constexpr int T = K / 16;   // 16 (QKV) or 8 (out-proj)

    // prologue: stages 0,1 stored; ldg(2) in regs
    ldgA(0); ldgB(0);
    stsA(0); stsB(0);
    ldgA(1); ldgB(1);
    stsA(1); stsB(1);
    ldgA(2); ldgB(2);
    __syncthreads();

    #pragma unroll 1
    for (int t = 0; t < T; t++) {
        compute(t);
        if (t + 2 < T) { stsA(t + 2); stsB(t + 2); }
        if (t + 3 < T) { ldgA(t + 3); ldgB(t + 3); }
        __syncthreads();
    }

    const int mg0 = mt * 128 + wm * 64;
    const int ng0 = nt * NT + wn * 64;
    uint32_t* Cw = (uint32_t*)Cg + (size_t)z * M * PW;

    if (MODE == 0) {
        // --- QKV epilogue: exp on q,k + pack fp16 + ksum ---
        #pragma unroll
        for (int mf = 0; mf < 4; mf++) {
            const int r0 = mg0 + mf * 16 + gp;
            float s0 = 0.f, s1 = 0.f;
            #pragma unroll
            for (int nf = 0; nf < 8; nf++) {
                const int wc = (ng0 >> 1) + nf * 4 + tq;
                float a0 = acc[mf][nf][0], a1 = acc[mf][nf][1];
                float a2 = acc[mf][nf][2], a3 = acc[mf][nf][3];
                if (mt < 2) {
                    a0 = __expf(a0); a1 = __expf(a1);
                    a2 = __expf(a2); a3 = __expf(a3);
                }
                s0 += a0 + a1; s1 += a2 + a3;
                Cw[(size_t)r0      * PW + wc] = pack2(a0, a1);
                Cw[(size_t)(r0+8)  * PW + wc] = pack2(a2, a3);
            }
            if (mt == 1) {
                s0 += __shfl_xor_sync(0xffffffffu, s0, 1);
                s0 += __shfl_xor_sync(0xffffffffu, s0, 2);
                s1 += __shfl_xor_sync(0xffffffffu, s1, 1);
                s1 += __shfl_xor_sync(0xffffffffu, s1, 2);
                if (tq == 0) {
                    const int rk  = wm * 64 + mf * 16 + gp;
                    const int rk8 = rk + 8;
                    atomicAdd(&g_ksum[(z * HEADS + (rk  >> 5)) * 32 + (rk  & 31)], s0);
                    atomicAdd(&g_ksum[(z * HEADS + (rk8 >> 5)) * 32 + (rk8 & 31)], s1);
                }
            }
        }
    } else {
        // --- OUT epilogue: bias + stats (fp32 accs), packed fp16 store ---
        float lsum = 0.f, lsq = 0.f;
        #pragma unroll
        for (int mf = 0; mf < 4; mf++) {
            const int r0 = mg0 + mf * 16 + gp;
            const float bv0 = bias[r0];
            const float bv1 = bias[r0 + 8];
            #pragma unroll
            for (int nf = 0; nf < 8; nf++) {
                const int wc = (ng0 >> 1) + nf * 4 + tq;
                float a0 = acc[mf][nf][0] + bv0, a1 = acc[mf][nf][1] + bv0;
                float a2 = acc[mf][nf][2] + bv1, a3 = acc[mf][nf][3] + bv1;
                lsum += a0 + a1 + a2 + a3;
                lsq  += a0 * a0 + a1 * a1 + a2 * a2 + a3 * a3;
                Cw[(size_t)r0      * PW + wc] = pack2(a0, a1);
                Cw[(size_t)(r0+8)  * PW + wc] = pack2(a2, a3);
            }
        }
        __shared__ float rs[8], rq[8];
        #pragma unroll
        for (int o = 16; o; o >>= 1) {
            lsum += __shfl_xor_sync(0xffffffffu, lsum, o);
            lsq  += __shfl_xor_sync(0xffffffffu, lsq,  o);
        }
        if (lane == 0) { rs[wid] = lsum; rq[wid] = lsq; }
        __syncthreads();
        if (tid == 0) {
            float s = 0.f, q = 0.f;
            #pragma unroll
            for (int w = 0; w < 8; w++) { s += rs[w]; q += rq[w]; }
            atomicAdd(&g_stats[2 * z + 0], s);
            atomicAdd(&g_stats[2 * z + 1], q);
        }
    }
}

// ---------------------------------------------------------------------------
// K2b: ctx = expk @ v^T, pure fp16 MMA, gmem-direct fragments (unchanged)
// ---------------------------------------------------------------------------
__global__ __launch_bounds__(256)
void k_ctx()
{
    __shared__ float red[8][32][33];

    const int nt = blockIdx.x, h = blockIdx.y, b = blockIdx.z;
    const int tid = threadIdx.x, lane = tid & 31, w = tid >> 5;
    const int gp = lane >> 2, tq = lane & 3;
    const int bh = b * HEADS + h;

    const uint32_t* kw = g_qkvh + ((size_t)b * O3 + HID     + h * DH) * PW;
    const uint32_t* vw = g_qkvh + ((size_t)b * O3 + 2 * HID + h * DH) * PW;
    const int wb0 = nt * 512 + w * 64;

    float acc[2][4][4];
    #pragma unroll
    for (int i = 0; i < 2; i++)
        #pragma unroll
        for (int j = 0; j < 4; j++)
            #pragma unroll
            for (int r = 0; r < 4; r++) acc[i][j][r] = 0.f;

    #pragma unroll
    for (int kk = 0; kk < 8; kk++) {
        const int w0 = wb0 + kk * 8 + tq, w1 = w0 + 4;
        uint32_t af[2][4], bf[4][2];
        #pragma unroll
        for (int m2 = 0; m2 < 2; m2++) {
            const int dm = m2 * 16;
            af[m2][0] = kw[(size_t)(dm + gp    ) * PW + w0];
            af[m2][1] = kw[(size_t)(dm + gp + 8) * PW + w0];
            af[m2][2] = kw[(size_t)(dm + gp    ) * PW + w1];
            af[m2][3] = kw[(size_t)(dm + gp + 8) * PW + w1];
        }
        #pragma unroll
        for (int n2 = 0; n2 < 4; n2++) {
            const int en = n2 * 8;
            bf[n2][0] = vw[(size_t)(en + gp) * PW + w0];
            bf[n2][1] = vw[(size_t)(en + gp) * PW + w1];
        }
        #pragma unroll
        for (int m2 = 0; m2 < 2; m2++)
            #pragma unroll
            for (int n2 = 0; n2 < 4; n2++)
                mma_f16(acc[m2][n2], af[m2], bf[n2]);
    }

    #pragma unroll
    for (int m2 = 0; m2 < 2; m2++) {
        const int d = m2 * 16 + gp;
        #pragma unroll
        for (int n2 = 0; n2 < 4; n2++) {
            const int e = n2 * 8 + tq * 2;
            red[w][d    ][e    ] = acc[m2][n2][0];
            red[w][d    ][e + 1] = acc[m2][n2][1];
            red[w][d + 8][e    ] = acc[m2][n2][2];
            red[w][d + 8][e + 1] = acc[m2][n2][3];
        }
    }
    __syncthreads();

    #pragma unroll
    for (int c = tid * 4; c < tid * 4 + 4; c++) {
        float s = 0.f;
        #pragma unroll
        for (int ww = 0; ww < 8; ww++) s += red[ww][c >> 5][c & 31];
        atomicAdd(&g_ctx[bh * 1024 + c], s);
    }
}

// ---------------------------------------------------------------------------
// K2c: out = (ctx/ksum)^T * expq * scale/colsum; fp16-packed output (unchanged)
// ---------------------------------------------------------------------------
__global__ __launch_bounds__(256)
void k_qout()
{
    __shared__ float qs[32][257];
    __shared__ float ctx[32][33];
    __shared__ float inv[32];
    __shared__ float cs[2][256];
    __shared__ float cinv[256];

    const int nt = blockIdx.x, h = blockIdx.y, b = blockIdx.z;
    const int tid = threadIdx.x;
    const int bh = b * HEADS + h;

    if (tid < 32) inv[tid] = 1.f / g_ksum[bh * 32 + tid];
    __syncthreads();
    #pragma unroll
    for (int i = tid; i < 1024; i += 256)
        ctx[i >> 5][i & 31] = g_ctx[bh * 1024 + i] * inv[i >> 5];

    const uint32_t* qw = g_qkvh + ((size_t)b * O3 + h * DH) * PW + nt * 128;
    const int wd = tid & 127, g2 = tid >> 7;
    float s0 = 0.f, s1 = 0.f;
    #pragma unroll
    for (int i = 0; i < 16; i++) {
        const int d = g2 + i * 2;
        float2 f = __half22float2(*(const __half2*)&qw[(size_t)d * PW + wd]);
        qs[d][2 * wd    ] = f.x;
        qs[d][2 * wd + 1] = f.y;
        s0 += f.x; s1 += f.y;
    }
    cs[g2][2 * wd    ] = s0;
    cs[g2][2 * wd + 1] = s1;
    __syncthreads();
    cinv[tid] = 0.17677669529663687f / (cs[0][tid] + cs[1][tid]);
    __syncthreads();

    const int w = tid >> 5, lane = tid & 31;
    float acc[4][8];
    #pragma unroll
    for (int i = 0; i < 4; i++)
        #pragma unroll
        for (int j = 0; j < 8; j++) acc[i][j] = 0.f;

    #pragma unroll
    for (int d = 0; d < 32; d++) {
        float ca[4], qa[8];
        #pragma unroll
        for (int i = 0; i < 4; i++) ca[i] = ctx[d][w * 4 + i];
        #pragma unroll
        for (int j = 0; j < 8; j++) qa[j] = qs[d][lane + 32 * j];
        #pragma unroll
        for (int i = 0; i < 4; i++)
            #pragma unroll
            for (int j = 0; j < 8; j++)
                acc[i][j] += ca[i] * qa[j];
    }

    uint32_t* obase = g_attn + ((size_t)b * (HID/2)) * NPIX + nt * 256;
    const int kw0 = h * 16 + w * 2;
    #pragma unroll
    for (int j = 0; j < 8; j++) {
        const int n = lane + 32 * j;
        const float civ = cinv[n];
        obase[(size_t)kw0       * NPIX + n] = pack2(acc[0][j] * civ, acc[1][j] * civ);
        obase[(size_t)(kw0 + 1) * NPIX + n] = pack2(acc[2][j] * civ, acc[3][j] * civ);
    }
}

// ---------------------------------------------------------------------------
// K4: GroupNorm from packed fp16 out-proj result -> fp32 d_out
// ---------------------------------------------------------------------------
__global__ __launch_bounds__(256)
void k_gn(float* __restrict__ out,
          const float* __restrict__ gn_w,
          const float* __restrict__ gn_b)
{
    const size_t widx = ((size_t)blockIdx.x * blockDim.x + threadIdx.x) * 2;
    const int b = (int)(widx >> 19);
    const int c = (int)((widx >> 11) & 255);

    const float invN = 1.f / (256.f * 4096.f);
    const float mean = g_stats[2 * b + 0] * invN;
    const float var  = g_stats[2 * b + 1] * invN - mean * mean;
    const float r    = rsqrtf(var + EPS);
    const float w    = gn_w[c] * r;
    const float bb   = gn_b[c] - mean * w;

    const uint2 pw = *(const uint2*)&g_outh[widx];
    const float2 f0 = __half22float2(*(const __half2*)&pw.x);
    const float2 f1 = __half22float2(*(const __half2*)&pw.y);
    float4 v;
    v.x = f0.x * w + bb;
    v.y = f0.y * w + bb;
    v.z = f1.x * w + bb;
    v.w = f1.y * w + bb;
    *(float4*)&out[widx * 2] = v;
}

// ---------------------------------------------------------------------------
// Launch
// ---------------------------------------------------------------------------
extern "C" void kernel_launch(void* const* d_in, const int* in_sizes, int n_in,
                              void* d_out, int out_size)
{
    const float* x     = (const float*)d_in[0];
    const float* w_qkv = (const float*)d_in[1];
    const float* w_out = (const float*)d_in[2];
    const float* b_out = (const float*)d_in[3];
    const float* gn_w  = (const float*)d_in[4];
    const float* gn_b  = (const float*)d_in[5];
    float* out = (float*)d_out;

    uint32_t *p_qkvh, *p_attn, *p_outh;
    cudaGetSymbolAddress((void**)&p_qkvh, g_qkvh);
    cudaGetSymbolAddress((void**)&p_attn, g_attn);
    cudaGetSymbolAddress((void**)&p_outh, g_outh);

    cudaFuncSetAttribute(k_mma<CIN, O3, 0, false>,
                         cudaFuncAttributeMaxDynamicSharedMemorySize, MMA_SMEM);
    cudaFuncSetAttribute(k_mma<HID, CIN, 1, true>,
                         cudaFuncAttributeMaxDynamicSharedMemorySize, MMA_SMEM);

    // launches 0-2: zero + pads (QKV GEMM stays at profiled slot 3)
    k_zero<<<(ZERO_N + 255) / 256, 256>>>();
    k_noop<<<1, 32>>>();
    k_noop<<<1, 32>>>();

    // launch 3: QKV projection (fp16 HMMA, 128x256 tile)
    k_mma<CIN, O3, 0, false>
        <<<dim3(O3 / 128, NPIX / NT, BATCH), 256, MMA_SMEM>>>(w_qkv, x, p_qkvh, nullptr);

    // attention core
    k_ctx <<<dim3(NPIX / 1024, HEADS, BATCH), 256>>>();
    k_qout<<<dim3(NPIX / 256,  HEADS, BATCH), 256>>>();

    // output projection + bias + stats -> packed fp16
    k_mma<HID, CIN, 1, true>
        <<<dim3(CIN / 128, NPIX / NT, BATCH), 256, MMA_SMEM>>>(w_out, p_attn, p_outh, b_out);

    // GroupNorm fp16 -> fp32 d_out
    k_gn<<<(BATCH * CIN * PW / 2) / 256, 256>>>(out, gn_w, gn_b);
}